// round 14
// baseline (speedup 1.0000x reference)
#include <cuda_runtime.h>
#include <cuda_fp16.h>
#include <math.h>

#define NN 2048
#define TT 20
#define KK 32
#define CC 32
#define OO 64
#define G4 256   // 4*OO

// Scratch (static device globals; no runtime allocation)
__device__ __half2 g_zh[TT * NN * (OO/2)];   // z fp16 (only intermediate)

// NaN-safe fast sigmoid / tanh (rel err ~1e-7, 2 MUFU each)
__device__ __forceinline__ float sigf(float x) {
    return __fdividef(1.0f, 1.0f + __expf(-x));
}
__device__ __forceinline__ float tanhf_fast(float x) {
    return 1.0f - __fdividef(2.0f, __expf(2.0f * x) + 1.0f);
}

// gather-max + center + bias for one (t, agent) row; lane-parallel over ch.
__device__ __forceinline__ __half2 gather_feat(const int* __restrict__ A,
                                               int t, int agent, int lane,
                                               float2 cb) {
    const int row = (t << 11) + agent;
    const int nb = A[(row << 5) + lane];
    __half2 m = __float2half2_rn(-60000.f);
#pragma unroll
    for (int k = 0; k < KK; k++) {
        int r = __shfl_sync(0xffffffffu, nb, k);
        __half2 v = __ldg(&g_zh[(((t << 11) + r) << 5) + lane]);
        m = __hmax2(m, v);
    }
    float2 mf = __half22float2(m);
    float2 zc = __half22float2(g_zh[(row << 5) + lane]);
    return __floats2half2_rn(mf.x - zc.x + cb.x, mf.y - zc.y + cb.y);
}

// ---------------------------------------------------------------------------
// K1 (tensor-core): z[rows x 64] = x[rows x 32] @ conv_w^T[32 x 64]
// (unchanged from R12)
// ---------------------------------------------------------------------------
__global__ __launch_bounds__(256) void k1_project(const float* __restrict__ x,
                                                  const float* __restrict__ conv_w) {
    __shared__ __half xs[128 * 40];   // 10 KB
    __shared__ __half zs[128 * 72];   // 18 KB staging for z

    const int tid = threadIdx.x;
    const int wid = tid >> 5;
    const int lane = tid & 31;
    const int gid = lane >> 2;
    const int tig = lane & 3;
    const int row0 = blockIdx.x << 7;

    unsigned b[8][2][2];
#pragma unroll
    for (int nt = 0; nt < 8; nt++) {
        const int n0 = (nt << 3) + gid;
        const float* wr = conv_w + n0 * 32;
#pragma unroll
        for (int ks = 0; ks < 2; ks++) {
            const int k0 = (ks << 4) + (tig << 1);
            float2 lo = *(const float2*)(wr + k0);
            float2 hi = *(const float2*)(wr + k0 + 8);
            __half2 p0 = __floats2half2_rn(lo.x, lo.y);
            __half2 p1 = __floats2half2_rn(hi.x, hi.y);
            b[nt][ks][0] = *(unsigned*)&p0;
            b[nt][ks][1] = *(unsigned*)&p1;
        }
    }

    {
        const float4* x4 = (const float4*)x;
#pragma unroll
        for (int it = 0; it < 4; it++) {
            int idx = tid + (it << 8);
            int rl = idx >> 3, c4 = idx & 7;
            int row = row0 + rl;
            int t = row >> 11, n = row & (NN - 1);
            float4 v = x4[((n * TT + t) << 3) + c4];
            *(__half2*)(xs + rl * 40 + (c4 << 2))     = __floats2half2_rn(v.x, v.y);
            *(__half2*)(xs + rl * 40 + (c4 << 2) + 2) = __floats2half2_rn(v.z, v.w);
        }
    }
    __syncthreads();

    const int wbase = wid << 4;
    unsigned a[2][4];
#pragma unroll
    for (int ks = 0; ks < 2; ks++) {
        const int col = (ks << 4) + (tig << 1);
        a[ks][0] = *(const unsigned*)(xs + (wbase + gid) * 40 + col);
        a[ks][1] = *(const unsigned*)(xs + (wbase + gid + 8) * 40 + col);
        a[ks][2] = *(const unsigned*)(xs + (wbase + gid) * 40 + col + 8);
        a[ks][3] = *(const unsigned*)(xs + (wbase + gid + 8) * 40 + col + 8);
    }

#pragma unroll
    for (int nt = 0; nt < 8; nt++) {
        float c0 = 0.f, c1 = 0.f, c2 = 0.f, c3 = 0.f;
#pragma unroll
        for (int ks = 0; ks < 2; ks++) {
            asm volatile(
                "mma.sync.aligned.m16n8k16.row.col.f32.f16.f16.f32 "
                "{%0,%1,%2,%3}, {%4,%5,%6,%7}, {%8,%9}, {%0,%1,%2,%3};"
                : "+f"(c0), "+f"(c1), "+f"(c2), "+f"(c3)
                : "r"(a[ks][0]), "r"(a[ks][1]), "r"(a[ks][2]), "r"(a[ks][3]),
                  "r"(b[nt][ks][0]), "r"(b[nt][ks][1]));
        }
        const int col = (nt << 3) + (tig << 1);
        *(__half2*)(zs + (wbase + gid) * 72 + col)     = __floats2half2_rn(c0, c1);
        *(__half2*)(zs + (wbase + gid + 8) * 72 + col) = __floats2half2_rn(c2, c3);
    }
    __syncthreads();

    {
        uint4* zg = ((uint4*)g_zh) + ((size_t)row0 << 3);
#pragma unroll
        for (int it = 0; it < 4; it++) {
            int idx = tid + (it << 8);
            int rl = idx >> 3, c = idx & 7;
            zg[idx] = ((const uint4*)(zs + rl * 72))[c];
        }
    }
}

// ---------------------------------------------------------------------------
// K234 (fused, pipelined): 256 blocks x 256 threads; block owns 8 agents,
// __launch_bounds__(256,2) -> 2 blocks/SM (16 warps).
// Warp w gathers feat for agent w (pipelined one step ahead, loads overlap
// the update+barrier of the previous step); per step one concatenated MMA
// gates = [feat | h] @ [w_ih | w_hh]^T (warp owns 32 cols: 4 nt x 8 ks);
// update spread over all 256 threads (2 channels each), c in registers.
// ---------------------------------------------------------------------------
__global__ __launch_bounds__(256, 2) void k234_lstm(const int* __restrict__ A,
                                                    const float* __restrict__ conv_b,
                                                    const float* __restrict__ w_ih,
                                                    const float* __restrict__ w_hh,
                                                    const float* __restrict__ b_ih,
                                                    const float* __restrict__ b_hh,
                                                    float* __restrict__ out,
                                                    int write_states) {
    __shared__ __half smA[16 * 136];   // rows 0-7: [feat | h]; rows 8-15 zero
    __shared__ float  g_s[8 * 260];    // gate pre-activations staging

    const int tid = threadIdx.x;
    const int wid = tid >> 5;        // 0..7
    const int lane = tid & 31;
    const int gid = lane >> 2;       // 0..7
    const int tig = lane & 3;        // 0..3
    const int ab = blockIdx.x << 3;  // agent base (8 per block)
    const int nbase = wid << 5;      // warp's 32 gate columns

    // ---- B fragments: concat [w_ih | w_hh], warp covers 32 cols ----
    unsigned b[4][8][2];
    float2 biasv[4];
#pragma unroll
    for (int nt = 0; nt < 4; nt++) {
        const int n0 = nbase + (nt << 3) + gid;
#pragma unroll
        for (int ks = 0; ks < 8; ks++) {
            const float* wr = (ks < 4 ? w_ih : w_hh) + n0 * 64;
            const int k0 = ((ks & 3) << 4) + (tig << 1);
            float2 lo = *(const float2*)(wr + k0);
            float2 hi = *(const float2*)(wr + k0 + 8);
            __half2 p0 = __floats2half2_rn(lo.x, lo.y);
            __half2 p1 = __floats2half2_rn(hi.x, hi.y);
            b[nt][ks][0] = *(unsigned*)&p0;
            b[nt][ks][1] = *(unsigned*)&p1;
        }
        const int col = nbase + (nt << 3) + (tig << 1);
        biasv[nt].x = b_ih[col] + b_hh[col];
        biasv[nt].y = b_ih[col + 1] + b_hh[col + 1];
    }

    for (int e = tid; e < 16 * 136; e += 256) smA[e] = __float2half(0.f);

    const float2 cb = ((const float2*)conv_b)[lane];
    const int a_u = tid >> 5;   // update agent == wid
    const int q = tid & 31;     // float2 chunk within 64 channels
    float2 c2 = make_float2(0.f, 0.f);
    float2 h_last = make_float2(0.f, 0.f);

    // ---- prologue: gather feat(0) for agent wid ----
    __half2 featreg = gather_feat(A, 0, ab + wid, lane, cb);
    __syncthreads();

    for (int t = 0; t < TT; t++) {
        // ---- commit this step's feat (gathered last iteration) ----
        *(__half2*)(smA + wid * 136 + (lane << 1)) = featreg;
        __syncthreads();   // feat(t) + h(t-1) visible to MMA

        // ---- concatenated MMA: warp's 32 columns ----
        unsigned afr[8][4];
#pragma unroll
        for (int ks = 0; ks < 8; ks++) {
            const int col = (ks << 4) + (tig << 1);
            afr[ks][0] = *(const unsigned*)(smA + gid * 136 + col);
            afr[ks][1] = *(const unsigned*)(smA + (gid + 8) * 136 + col);
            afr[ks][2] = *(const unsigned*)(smA + gid * 136 + col + 8);
            afr[ks][3] = *(const unsigned*)(smA + (gid + 8) * 136 + col + 8);
        }
#pragma unroll
        for (int nt = 0; nt < 4; nt++) {
            float c0 = 0.f, c1 = 0.f, d2 = 0.f, d3 = 0.f;
#pragma unroll
            for (int ks = 0; ks < 8; ks++) {
                asm volatile(
                    "mma.sync.aligned.m16n8k16.row.col.f32.f16.f16.f32 "
                    "{%0,%1,%2,%3}, {%4,%5,%6,%7}, {%8,%9}, {%0,%1,%2,%3};"
                    : "+f"(c0), "+f"(c1), "+f"(d2), "+f"(d3)
                    : "r"(afr[ks][0]), "r"(afr[ks][1]), "r"(afr[ks][2]), "r"(afr[ks][3]),
                      "r"(b[nt][ks][0]), "r"(b[nt][ks][1]));
            }
            const int col = nbase + (nt << 3) + (tig << 1);
            g_s[gid * 260 + col]     = c0 + biasv[nt].x;   // rows 8-15 discarded
            g_s[gid * 260 + col + 1] = c1 + biasv[nt].y;
        }

        // ---- pipelined gather for t+1 (overlaps barrier + update) ----
        if (t + 1 < TT)
            featreg = gather_feat(A, t + 1, ab + wid, lane, cb);
        __syncthreads();   // g_s ready

        // ---- nonlinear update: thread owns (agent a_u, 2 channels) ----
        const float* gr = g_s + a_u * 260 + (q << 1);
        float2 gi = *(const float2*)(gr);
        float2 gf = *(const float2*)(gr + 64);
        float2 gg = *(const float2*)(gr + 128);
        float2 go = *(const float2*)(gr + 192);

        c2.x = sigf(gf.x) * c2.x + sigf(gi.x) * tanhf_fast(gg.x);
        c2.y = sigf(gf.y) * c2.y + sigf(gi.y) * tanhf_fast(gg.y);

        float2 h2;
        h2.x = sigf(go.x) * tanhf_fast(c2.x);
        h2.y = sigf(go.y) * tanhf_fast(c2.y);
        h_last = h2;

        // h -> smA cols 64-127 (disjoint from feat cols / g_s; ordered by
        // the next iteration's barrier-1 before MMA reads)
        *(__half2*)(smA + a_u * 136 + 64 + (q << 1)) = __floats2half2_rn(h2.x, h2.y);
        *(float2*)(out + (((size_t)(ab + a_u) * TT + t) << 6) + (q << 1)) = h2;
    }

    if (write_states) {
        float2* hn = (float2*)(out + (size_t)NN * TT * OO);
        float2* cn = (float2*)(out + (size_t)NN * TT * OO + (size_t)NN * OO);
        hn[((ab + a_u) << 5) + q] = h_last;
        cn[((ab + a_u) << 5) + q] = c2;
    }
}

// ---------------------------------------------------------------------------
extern "C" void kernel_launch(void* const* d_in, const int* in_sizes, int n_in,
                              void* d_out, int out_size) {
    const float* x      = (const float*)d_in[0];
    const int*   A      = (const int*)  d_in[1];
    const float* conv_w = (const float*)d_in[2];
    const float* conv_b = (const float*)d_in[3];
    const float* w_ih   = (const float*)d_in[4];
    const float* w_hh   = (const float*)d_in[5];
    const float* b_ih   = (const float*)d_in[6];
    const float* b_hh   = (const float*)d_in[7];
    float* out = (float*)d_out;

    const long main_sz = (long)NN * TT * OO;
    int write_states = (out_size >= main_sz + 2L * NN * OO) ? 1 : 0;

    k1_project<<<(TT * NN) / 128, 256>>>(x, conv_w);
    k234_lstm<<<NN / 8, 256>>>(A, conv_b, w_ih, w_hh, b_ih, b_hh, out, write_states);
}

// round 15
// speedup vs baseline: 1.0877x; 1.0877x over previous
#include <cuda_runtime.h>
#include <cuda_fp16.h>
#include <math.h>

#define NN 2048
#define TT 20
#define KK 32
#define CC 32
#define OO 64
#define G4 256   // 4*OO

// Scratch (static device globals; no runtime allocation)
__device__ __half2 g_zh[TT * NN * (OO/2)];   // z fp16 (only intermediate)

// NaN-safe fast sigmoid / tanh (rel err ~1e-7, 2 MUFU each)
__device__ __forceinline__ float sigf(float x) {
    return __fdividef(1.0f, 1.0f + __expf(-x));
}
__device__ __forceinline__ float tanhf_fast(float x) {
    return 1.0f - __fdividef(2.0f, __expf(2.0f * x) + 1.0f);
}

// ---------------------------------------------------------------------------
// K1 (tensor-core): z[rows x 64] = x[rows x 32] @ conv_w^T[32 x 64]
// (unchanged from R12)
// ---------------------------------------------------------------------------
__global__ __launch_bounds__(256) void k1_project(const float* __restrict__ x,
                                                  const float* __restrict__ conv_w) {
    __shared__ __half xs[128 * 40];   // 10 KB
    __shared__ __half zs[128 * 72];   // 18 KB staging for z

    const int tid = threadIdx.x;
    const int wid = tid >> 5;
    const int lane = tid & 31;
    const int gid = lane >> 2;
    const int tig = lane & 3;
    const int row0 = blockIdx.x << 7;

    unsigned b[8][2][2];
#pragma unroll
    for (int nt = 0; nt < 8; nt++) {
        const int n0 = (nt << 3) + gid;
        const float* wr = conv_w + n0 * 32;
#pragma unroll
        for (int ks = 0; ks < 2; ks++) {
            const int k0 = (ks << 4) + (tig << 1);
            float2 lo = *(const float2*)(wr + k0);
            float2 hi = *(const float2*)(wr + k0 + 8);
            __half2 p0 = __floats2half2_rn(lo.x, lo.y);
            __half2 p1 = __floats2half2_rn(hi.x, hi.y);
            b[nt][ks][0] = *(unsigned*)&p0;
            b[nt][ks][1] = *(unsigned*)&p1;
        }
    }

    {
        const float4* x4 = (const float4*)x;
#pragma unroll
        for (int it = 0; it < 4; it++) {
            int idx = tid + (it << 8);
            int rl = idx >> 3, c4 = idx & 7;
            int row = row0 + rl;
            int t = row >> 11, n = row & (NN - 1);
            float4 v = x4[((n * TT + t) << 3) + c4];
            *(__half2*)(xs + rl * 40 + (c4 << 2))     = __floats2half2_rn(v.x, v.y);
            *(__half2*)(xs + rl * 40 + (c4 << 2) + 2) = __floats2half2_rn(v.z, v.w);
        }
    }
    __syncthreads();

    const int wbase = wid << 4;
    unsigned a[2][4];
#pragma unroll
    for (int ks = 0; ks < 2; ks++) {
        const int col = (ks << 4) + (tig << 1);
        a[ks][0] = *(const unsigned*)(xs + (wbase + gid) * 40 + col);
        a[ks][1] = *(const unsigned*)(xs + (wbase + gid + 8) * 40 + col);
        a[ks][2] = *(const unsigned*)(xs + (wbase + gid) * 40 + col + 8);
        a[ks][3] = *(const unsigned*)(xs + (wbase + gid + 8) * 40 + col + 8);
    }

#pragma unroll
    for (int nt = 0; nt < 8; nt++) {
        float c0 = 0.f, c1 = 0.f, c2 = 0.f, c3 = 0.f;
#pragma unroll
        for (int ks = 0; ks < 2; ks++) {
            asm volatile(
                "mma.sync.aligned.m16n8k16.row.col.f32.f16.f16.f32 "
                "{%0,%1,%2,%3}, {%4,%5,%6,%7}, {%8,%9}, {%0,%1,%2,%3};"
                : "+f"(c0), "+f"(c1), "+f"(c2), "+f"(c3)
                : "r"(a[ks][0]), "r"(a[ks][1]), "r"(a[ks][2]), "r"(a[ks][3]),
                  "r"(b[nt][ks][0]), "r"(b[nt][ks][1]));
        }
        const int col = (nt << 3) + (tig << 1);
        *(__half2*)(zs + (wbase + gid) * 72 + col)     = __floats2half2_rn(c0, c1);
        *(__half2*)(zs + (wbase + gid + 8) * 72 + col) = __floats2half2_rn(c2, c3);
    }
    __syncthreads();

    {
        uint4* zg = ((uint4*)g_zh) + ((size_t)row0 << 3);
#pragma unroll
        for (int it = 0; it < 4; it++) {
            int idx = tid + (it << 8);
            int rl = idx >> 3, c = idx & 7;
            zg[idx] = ((const uint4*)(zs + rl * 72))[c];
        }
    }
}

// ---------------------------------------------------------------------------
// K234 (fused, fully pre-gathered): 256 blocks x 256 threads; block owns 8
// agents; 2 blocks/SM.
// Phase 1: all 8 agents x 20 steps of feat gathered into smF (two steps
//          interleaved per warp for MLP); gathers leave the critical path.
// Phase 2: per step ONE concatenated MMA, gate-aligned columns so thread
//          (gid,tig) holds all 4 gates of (agent gid, 2 channels) in
//          registers; update in-register; h ping-pong in smH; ONE barrier
//          per step.  No g_s, no global gates.
// ---------------------------------------------------------------------------
__global__ __launch_bounds__(256, 2) void k234_lstm(const int* __restrict__ A,
                                                    const float* __restrict__ conv_b,
                                                    const float* __restrict__ w_ih,
                                                    const float* __restrict__ w_hh,
                                                    const float* __restrict__ b_ih,
                                                    const float* __restrict__ b_hh,
                                                    float* __restrict__ out,
                                                    int write_states) {
    __shared__ __half smF[TT * 8 * 72];   // feat, 160 rows x 72 (22.5 KB)
    __shared__ __half smH[2][16 * 72];    // h ping-pong, rows 8-15 stay zero

    const int tid = threadIdx.x;
    const int wid = tid >> 5;        // 0..7
    const int lane = tid & 31;
    const int gid = lane >> 2;       // 0..7 (= agent in update phase)
    const int tig = lane & 3;        // 0..3
    const int ab = blockIdx.x << 3;  // agent base (8 per block)
    const int chb = (wid << 3) + (tig << 1);  // this thread's 2 channels

    // ---- B fragments, gate-aligned: nt = gate, cols nt*64 + wid*8 + ... ----
    unsigned b[4][8][2];
    float2 biasv[4];
#pragma unroll
    for (int nt = 0; nt < 4; nt++) {
        const int n0 = (nt << 6) + (wid << 3) + gid;
#pragma unroll
        for (int ks = 0; ks < 8; ks++) {
            const float* wr = (ks < 4 ? w_ih : w_hh) + n0 * 64;
            const int k0 = ((ks & 3) << 4) + (tig << 1);
            float2 lo = *(const float2*)(wr + k0);
            float2 hi = *(const float2*)(wr + k0 + 8);
            __half2 p0 = __floats2half2_rn(lo.x, lo.y);
            __half2 p1 = __floats2half2_rn(hi.x, hi.y);
            b[nt][ks][0] = *(unsigned*)&p0;
            b[nt][ks][1] = *(unsigned*)&p1;
        }
        const int col = (nt << 6) + chb;
        biasv[nt].x = b_ih[col] + b_hh[col];
        biasv[nt].y = b_ih[col + 1] + b_hh[col + 1];
    }

    // zero both h buffers (incl. rows 8-15 = permanent MMA zero rows)
    for (int e = tid; e < 16 * 72; e += 256) {
        smH[0][e] = __float2half(0.f);
        smH[1][e] = __float2half(0.f);
    }

    const float2 cb = ((const float2*)conv_b)[lane];

    // ---- Phase 1: gather all feat; warp wid owns agent wid, 2 t's at once --
    const int agent = ab + wid;
    for (int j = 0; j < TT; j += 2) {
        const int row0 = (j << 11) + agent;
        const int row1 = ((j + 1) << 11) + agent;
        const int nb0 = A[(row0 << 5) + lane];
        const int nb1 = A[(row1 << 5) + lane];
        __half2 m0 = __float2half2_rn(-60000.f);
        __half2 m1 = m0;
#pragma unroll
        for (int k = 0; k < KK; k++) {
            int r0 = __shfl_sync(0xffffffffu, nb0, k);
            int r1 = __shfl_sync(0xffffffffu, nb1, k);
            __half2 v0 = __ldg(&g_zh[(((j << 11) + r0) << 5) + lane]);
            __half2 v1 = __ldg(&g_zh[((((j + 1) << 11) + r1) << 5) + lane]);
            m0 = __hmax2(m0, v0);
            m1 = __hmax2(m1, v1);
        }
        float2 mf0 = __half22float2(m0), zc0 = __half22float2(g_zh[(row0 << 5) + lane]);
        float2 mf1 = __half22float2(m1), zc1 = __half22float2(g_zh[(row1 << 5) + lane]);
        *(__half2*)(smF + ((j << 3) + wid) * 72 + (lane << 1)) =
            __floats2half2_rn(mf0.x - zc0.x + cb.x, mf0.y - zc0.y + cb.y);
        *(__half2*)(smF + (((j + 1) << 3) + wid) * 72 + (lane << 1)) =
            __floats2half2_rn(mf1.x - zc1.x + cb.x, mf1.y - zc1.y + cb.y);
    }
    __syncthreads();

    float2 c2 = make_float2(0.f, 0.f);
    float2 h_last = make_float2(0.f, 0.f);

    for (int t = 0; t < TT; t++) {
        const __half* hb = smH[t & 1];
        const __half* fb = smF + ((t << 3)) * 72;

        // ---- A fragments: feat (ks 0-3) + h (ks 4-7); upper rows zero ----
        unsigned afr[8][4];
#pragma unroll
        for (int ks = 0; ks < 4; ks++) {
            const int col = (ks << 4) + (tig << 1);
            afr[ks][0] = *(const unsigned*)(fb + gid * 72 + col);
            afr[ks][1] = *(const unsigned*)(hb + (gid + 8) * 72 + col);  // zeros
            afr[ks][2] = *(const unsigned*)(fb + gid * 72 + col + 8);
            afr[ks][3] = *(const unsigned*)(hb + (gid + 8) * 72 + col + 8);  // zeros
        }
#pragma unroll
        for (int ks = 4; ks < 8; ks++) {
            const int col = ((ks - 4) << 4) + (tig << 1);
            afr[ks][0] = *(const unsigned*)(hb + gid * 72 + col);
            afr[ks][1] = *(const unsigned*)(hb + (gid + 8) * 72 + col);  // zeros
            afr[ks][2] = *(const unsigned*)(hb + gid * 72 + col + 8);
            afr[ks][3] = *(const unsigned*)(hb + (gid + 8) * 72 + col + 8);  // zeros
        }

        // ---- gate-aligned MMAs: nt = gate; accumulate f32 ----
        float gac[4][2];
#pragma unroll
        for (int nt = 0; nt < 4; nt++) {
            float c0 = 0.f, c1 = 0.f, d2 = 0.f, d3 = 0.f;
#pragma unroll
            for (int ks = 0; ks < 8; ks++) {
                asm volatile(
                    "mma.sync.aligned.m16n8k16.row.col.f32.f16.f16.f32 "
                    "{%0,%1,%2,%3}, {%4,%5,%6,%7}, {%8,%9}, {%0,%1,%2,%3};"
                    : "+f"(c0), "+f"(c1), "+f"(d2), "+f"(d3)
                    : "r"(afr[ks][0]), "r"(afr[ks][1]), "r"(afr[ks][2]), "r"(afr[ks][3]),
                      "r"(b[nt][ks][0]), "r"(b[nt][ks][1]));
            }
            gac[nt][0] = c0 + biasv[nt].x;
            gac[nt][1] = c1 + biasv[nt].y;
        }

        // ---- in-register update: agent gid, channels chb, chb+1 ----
        float2 gi = make_float2(gac[0][0], gac[0][1]);
        float2 gf = make_float2(gac[1][0], gac[1][1]);
        float2 gg = make_float2(gac[2][0], gac[2][1]);
        float2 go = make_float2(gac[3][0], gac[3][1]);

        c2.x = sigf(gf.x) * c2.x + sigf(gi.x) * tanhf_fast(gg.x);
        c2.y = sigf(gf.y) * c2.y + sigf(gi.y) * tanhf_fast(gg.y);

        float2 h2;
        h2.x = sigf(go.x) * tanhf_fast(c2.x);
        h2.y = sigf(go.y) * tanhf_fast(c2.y);
        h_last = h2;

        // h -> other buffer (read next step), out -> global
        *(__half2*)(smH[(t + 1) & 1] + gid * 72 + chb) = __floats2half2_rn(h2.x, h2.y);
        *(float2*)(out + (((size_t)(ab + gid) * TT + t) << 6) + chb) = h2;

        __syncthreads();   // h(t) visible before step t+1 reads
    }

    if (write_states) {
        float2* hn = (float2*)(out + (size_t)NN * TT * OO);
        float2* cn = (float2*)(out + (size_t)NN * TT * OO + (size_t)NN * OO);
        hn[((ab + gid) << 5) + (chb >> 1)] = h_last;
        cn[((ab + gid) << 5) + (chb >> 1)] = c2;
    }
}

// ---------------------------------------------------------------------------
extern "C" void kernel_launch(void* const* d_in, const int* in_sizes, int n_in,
                              void* d_out, int out_size) {
    const float* x      = (const float*)d_in[0];
    const int*   A      = (const int*)  d_in[1];
    const float* conv_w = (const float*)d_in[2];
    const float* conv_b = (const float*)d_in[3];
    const float* w_ih   = (const float*)d_in[4];
    const float* w_hh   = (const float*)d_in[5];
    const float* b_ih   = (const float*)d_in[6];
    const float* b_hh   = (const float*)d_in[7];
    float* out = (float*)d_out;

    const long main_sz = (long)NN * TT * OO;
    int write_states = (out_size >= main_sz + 2L * NN * OO) ? 1 : 0;

    k1_project<<<(TT * NN) / 128, 256>>>(x, conv_w);
    k234_lstm<<<NN / 8, 256>>>(A, conv_b, w_ih, w_hh, b_ih, b_hh, out, write_states);
}